// round 3
// baseline (speedup 1.0000x reference)
#include <cuda_runtime.h>
#include <cstdint>

#define LUT_MAX 512

// 8 elements per thread (2 x float4 per stream), flat grid, plain loads so
// ptxas front-batches all 6 independent LDG.128s.
template <bool MASK_AS_FLOAT>
__global__ __launch_bounds__(256)
void octvol_kernel(const int4* __restrict__ labels4,
                   const float4* __restrict__ par4,
                   const float4* __restrict__ tex4,
                   const float* __restrict__ lut,
                   int lut_n,
                   float4* __restrict__ out_vol4,
                   void* __restrict__ out_mask,
                   int n4)
{
    __shared__ float s_lut[LUT_MAX];
    for (int i = threadIdx.x; i < lut_n; i += blockDim.x)
        s_lut[i] = lut[i];
    __syncthreads();

    int idx = (blockIdx.x * blockDim.x + threadIdx.x) * 2;
    if (idx >= n4) return;

    // ---- loads, front-batched ----
    int4   lbA = labels4[idx];
    float4 paA = par4[idx];
    float4 txA = tex4[idx];
    bool has_b = (idx + 1) < n4;
    int4   lbB = has_b ? labels4[idx + 1] : lbA;
    float4 paB = has_b ? par4[idx + 1]    : paA;
    float4 txB = has_b ? tex4[idx + 1]    : txA;

    // ---- element A ----
    float a0 = s_lut[lbA.x] * txA.x; if (a0 == 0.0f) a0 = 1.0f;
    float a1 = s_lut[lbA.y] * txA.y; if (a1 == 0.0f) a1 = 1.0f;
    float a2 = s_lut[lbA.z] * txA.z; if (a2 == 0.0f) a2 = 1.0f;
    float a3 = s_lut[lbA.w] * txA.w; if (a3 == 0.0f) a3 = 1.0f;
    float4 oA = make_float4(paA.x * a0, paA.y * a1, paA.z * a2, paA.w * a3);

    // ---- element B ----
    float b0 = s_lut[lbB.x] * txB.x; if (b0 == 0.0f) b0 = 1.0f;
    float b1 = s_lut[lbB.y] * txB.y; if (b1 == 0.0f) b1 = 1.0f;
    float b2 = s_lut[lbB.z] * txB.z; if (b2 == 0.0f) b2 = 1.0f;
    float b3 = s_lut[lbB.w] * txB.w; if (b3 == 0.0f) b3 = 1.0f;
    float4 oB = make_float4(paB.x * b0, paB.y * b1, paB.z * b2, paB.w * b3);

    out_vol4[idx] = oA;
    if (has_b) out_vol4[idx + 1] = oB;

    if (MASK_AS_FLOAT) {
        float4* mask4 = reinterpret_cast<float4*>(out_mask);
        float4 mA = make_float4(lbA.x ? 1.0f : 0.0f, lbA.y ? 1.0f : 0.0f,
                                lbA.z ? 1.0f : 0.0f, lbA.w ? 1.0f : 0.0f);
        mask4[idx] = mA;
        if (has_b) {
            float4 mB = make_float4(lbB.x ? 1.0f : 0.0f, lbB.y ? 1.0f : 0.0f,
                                    lbB.z ? 1.0f : 0.0f, lbB.w ? 1.0f : 0.0f);
            mask4[idx + 1] = mB;
        }
    } else {
        uchar4* mask1 = reinterpret_cast<uchar4*>(out_mask);
        uchar4 mA = make_uchar4(lbA.x ? 1 : 0, lbA.y ? 1 : 0,
                                lbA.z ? 1 : 0, lbA.w ? 1 : 0);
        mask1[idx] = mA;
        if (has_b) {
            uchar4 mB = make_uchar4(lbB.x ? 1 : 0, lbB.y ? 1 : 0,
                                    lbB.z ? 1 : 0, lbB.w ? 1 : 0);
            mask1[idx + 1] = mB;
        }
    }
}

extern "C" void kernel_launch(void* const* d_in, const int* in_sizes, int n_in,
                              void* d_out, int out_size)
{
    const int*   labels = (const int*)  d_in[0];
    const float* par    = (const float*)d_in[1];
    const float* tex    = (const float*)d_in[2];
    const float* lut    = (const float*)d_in[3];

    int n     = in_sizes[0];
    int lut_n = in_sizes[3];
    int n4    = n / 4;

    float* out_vol = (float*)d_out;

    dim3 block(256);
    int threads_needed = (n4 + 1) / 2;
    dim3 grid((threads_needed + 255) / 256);

    if (out_size >= 2 * n) {
        void* out_mask = (void*)(out_vol + n);
        octvol_kernel<true><<<grid, block>>>(
            (const int4*)labels, (const float4*)par, (const float4*)tex,
            lut, lut_n, (float4*)out_vol, out_mask, n4);
    } else {
        void* out_mask = (void*)((char*)d_out + (size_t)n * sizeof(float));
        octvol_kernel<false><<<grid, block>>>(
            (const int4*)labels, (const float4*)par, (const float4*)tex,
            lut, lut_n, (float4*)out_vol, out_mask, n4);
    }
}

// round 4
// speedup vs baseline: 1.1197x; 1.1197x over previous
#include <cuda_runtime.h>
#include <cstdint>

#define LUT_MAX 512

// 8 elements per thread: block owns a contiguous 512-float4 chunk per stream;
// thread t handles chunk[t] and chunk[t+256]. Every LDG/STG warp-contiguous.
template <bool MASK_AS_FLOAT>
__global__ __launch_bounds__(256)
void octvol_kernel(const int4* __restrict__ labels4,
                   const float4* __restrict__ par4,
                   const float4* __restrict__ tex4,
                   const float* __restrict__ lut,
                   int lut_n,
                   float4* __restrict__ out_vol4,
                   void* __restrict__ out_mask,
                   int n4)
{
    __shared__ float s_lut[LUT_MAX];
    for (int i = threadIdx.x; i < lut_n; i += blockDim.x)
        s_lut[i] = lut[i];
    __syncthreads();

    int base = blockIdx.x * 512;
    int iA = base + threadIdx.x;
    int iB = iA + 256;
    if (iA >= n4) return;
    bool has_b = iB < n4;

    // ---- front-batched, fully coalesced loads ----
    int4   lbA = labels4[iA];
    float4 paA = par4[iA];
    float4 txA = tex4[iA];
    int4   lbB = has_b ? labels4[iB] : lbA;
    float4 paB = has_b ? par4[iB]    : paA;
    float4 txB = has_b ? tex4[iB]    : txA;

    float a0 = s_lut[lbA.x] * txA.x; if (a0 == 0.0f) a0 = 1.0f;
    float a1 = s_lut[lbA.y] * txA.y; if (a1 == 0.0f) a1 = 1.0f;
    float a2 = s_lut[lbA.z] * txA.z; if (a2 == 0.0f) a2 = 1.0f;
    float a3 = s_lut[lbA.w] * txA.w; if (a3 == 0.0f) a3 = 1.0f;
    float4 oA = make_float4(paA.x * a0, paA.y * a1, paA.z * a2, paA.w * a3);

    float b0 = s_lut[lbB.x] * txB.x; if (b0 == 0.0f) b0 = 1.0f;
    float b1 = s_lut[lbB.y] * txB.y; if (b1 == 0.0f) b1 = 1.0f;
    float b2 = s_lut[lbB.z] * txB.z; if (b2 == 0.0f) b2 = 1.0f;
    float b3 = s_lut[lbB.w] * txB.w; if (b3 == 0.0f) b3 = 1.0f;
    float4 oB = make_float4(paB.x * b0, paB.y * b1, paB.z * b2, paB.w * b3);

    out_vol4[iA] = oA;
    if (has_b) out_vol4[iB] = oB;

    if (MASK_AS_FLOAT) {
        float4* mask4 = reinterpret_cast<float4*>(out_mask);
        mask4[iA] = make_float4(lbA.x ? 1.0f : 0.0f, lbA.y ? 1.0f : 0.0f,
                                lbA.z ? 1.0f : 0.0f, lbA.w ? 1.0f : 0.0f);
        if (has_b)
            mask4[iB] = make_float4(lbB.x ? 1.0f : 0.0f, lbB.y ? 1.0f : 0.0f,
                                    lbB.z ? 1.0f : 0.0f, lbB.w ? 1.0f : 0.0f);
    } else {
        uchar4* mask1 = reinterpret_cast<uchar4*>(out_mask);
        mask1[iA] = make_uchar4(lbA.x ? 1 : 0, lbA.y ? 1 : 0,
                                lbA.z ? 1 : 0, lbA.w ? 1 : 0);
        if (has_b)
            mask1[iB] = make_uchar4(lbB.x ? 1 : 0, lbB.y ? 1 : 0,
                                    lbB.z ? 1 : 0, lbB.w ? 1 : 0);
    }
}

extern "C" void kernel_launch(void* const* d_in, const int* in_sizes, int n_in,
                              void* d_out, int out_size)
{
    const int*   labels = (const int*)  d_in[0];
    const float* par    = (const float*)d_in[1];
    const float* tex    = (const float*)d_in[2];
    const float* lut    = (const float*)d_in[3];

    int n     = in_sizes[0];
    int lut_n = in_sizes[3];
    int n4    = n / 4;

    float* out_vol = (float*)d_out;

    dim3 block(256);
    dim3 grid((n4 + 511) / 512);

    if (out_size >= 2 * n) {
        void* out_mask = (void*)(out_vol + n);
        octvol_kernel<true><<<grid, block>>>(
            (const int4*)labels, (const float4*)par, (const float4*)tex,
            lut, lut_n, (float4*)out_vol, out_mask, n4);
    } else {
        void* out_mask = (void*)((char*)d_out + (size_t)n * sizeof(float));
        octvol_kernel<false><<<grid, block>>>(
            (const int4*)labels, (const float4*)par, (const float4*)tex,
            lut, lut_n, (float4*)out_vol, out_mask, n4);
    }
}